// round 17
// baseline (speedup 1.0000x reference)
#include <cuda_runtime.h>
#include <float.h>

// Per-channel min/max over [C, N] fp32 (C=1024, N=32768).
// R16 probe: single-wave persistent layout. Grid = C/2 CTAs (512), each CTA
// handles 2 adjacent channels (one contiguous 256KB stream). 512 CTAs fit
// inside the 592-slot (148 SM x occ 4) capacity -> exactly one wave, no
// wave-2 quantization tail. 512 threads, occ cap 4, guard-free unrolled
// float4 stream (same inner loop as the converged R13 kernel).

__global__ void __launch_bounds__(512, 4)
minmax_pair_kernel(const float4* __restrict__ in, float* __restrict__ out,
                   int C, int N4) {
    const int b = blockIdx.x;                 // pair index
    const int iters = N4 >> 9;                // N4 / 512 (16 for N=32768)

    __shared__ float smn[16], smx[16];
    const int wid = threadIdx.x >> 5;
    const int lid = threadIdx.x & 31;

    #pragma unroll
    for (int ch = 0; ch < 2; ++ch) {
        const int c = b * 2 + ch;
        const float4* __restrict__ p = in + (size_t)c * N4 + threadIdx.x;

        float mn = FLT_MAX;
        float mx = -FLT_MAX;

        #pragma unroll 16
        for (int k = 0; k < iters; ++k) {
            float4 v = p[(size_t)k * 512];
            mn = fminf(mn, fminf(fminf(v.x, v.y), fminf(v.z, v.w)));
            mx = fmaxf(mx, fmaxf(fmaxf(v.x, v.y), fmaxf(v.z, v.w)));
        }

        // Warp butterfly reduction
        #pragma unroll
        for (int o = 16; o > 0; o >>= 1) {
            mn = fminf(mn, __shfl_xor_sync(0xffffffffu, mn, o));
            mx = fmaxf(mx, __shfl_xor_sync(0xffffffffu, mx, o));
        }

        if (ch == 1) __syncthreads();   // reuse smn/smx safely
        if (lid == 0) { smn[wid] = mn; smx[wid] = mx; }
        __syncthreads();

        if (wid == 0) {
            mn = (lid < 16) ? smn[lid] : FLT_MAX;
            mx = (lid < 16) ? smx[lid] : -FLT_MAX;
            #pragma unroll
            for (int o = 8; o > 0; o >>= 1) {
                mn = fminf(mn, __shfl_xor_sync(0xffffffffu, mn, o));
                mx = fmaxf(mx, __shfl_xor_sync(0xffffffffu, mx, o));
            }
            if (lid == 0) out[c]     = mn;   // min_vals
            if (lid == 1) out[C + c] = mx;   // max_vals
        }
    }
}

// Converged R13 kernel (best measured: 23.49us) — used when C is odd.
__global__ void __launch_bounds__(512, 4)
minmax_final_kernel(const float4* __restrict__ in, float* __restrict__ out,
                    int C, int N4) {
    const int c = blockIdx.x;
    const float4* __restrict__ p = in + (size_t)c * N4 + threadIdx.x;
    const int iters = N4 >> 9;

    float mn = FLT_MAX, mx = -FLT_MAX;
    #pragma unroll 16
    for (int k = 0; k < iters; ++k) {
        float4 v = p[(size_t)k * 512];
        mn = fminf(mn, fminf(fminf(v.x, v.y), fminf(v.z, v.w)));
        mx = fmaxf(mx, fmaxf(fmaxf(v.x, v.y), fmaxf(v.z, v.w)));
    }
    #pragma unroll
    for (int o = 16; o > 0; o >>= 1) {
        mn = fminf(mn, __shfl_xor_sync(0xffffffffu, mn, o));
        mx = fmaxf(mx, __shfl_xor_sync(0xffffffffu, mx, o));
    }
    __shared__ float smn[16], smx[16];
    const int wid = threadIdx.x >> 5, lid = threadIdx.x & 31;
    if (lid == 0) { smn[wid] = mn; smx[wid] = mx; }
    __syncthreads();
    if (wid == 0) {
        mn = (lid < 16) ? smn[lid] : FLT_MAX;
        mx = (lid < 16) ? smx[lid] : -FLT_MAX;
        #pragma unroll
        for (int o = 8; o > 0; o >>= 1) {
            mn = fminf(mn, __shfl_xor_sync(0xffffffffu, mn, o));
            mx = fmaxf(mx, __shfl_xor_sync(0xffffffffu, mx, o));
        }
        if (lid == 0) out[c]     = mn;
        if (lid == 1) out[C + c] = mx;
    }
}

// Fallback: one CTA per channel, scalar-safe (any N).
__global__ void __launch_bounds__(256)
minmax_simple_kernel(const float* __restrict__ in, float* __restrict__ out,
                     int C, int N) {
    const int c = blockIdx.x;
    const float* row = in + (size_t)c * N;
    float mn = FLT_MAX, mx = -FLT_MAX;
    for (int i = threadIdx.x; i < N; i += 256) {
        float v = row[i];
        mn = fminf(mn, v);
        mx = fmaxf(mx, v);
    }
    #pragma unroll
    for (int o = 16; o > 0; o >>= 1) {
        mn = fminf(mn, __shfl_xor_sync(0xffffffffu, mn, o));
        mx = fmaxf(mx, __shfl_xor_sync(0xffffffffu, mx, o));
    }
    __shared__ float smn[8], smx[8];
    const int wid = threadIdx.x >> 5, lid = threadIdx.x & 31;
    if (lid == 0) { smn[wid] = mn; smx[wid] = mx; }
    __syncthreads();
    if (threadIdx.x == 0) {
        #pragma unroll
        for (int w = 1; w < 8; ++w) {
            mn = fminf(mn, smn[w]);
            mx = fmaxf(mx, smx[w]);
        }
        out[c] = mn;
        out[C + c] = mx;
    }
}

extern "C" void kernel_launch(void* const* d_in, const int* in_sizes, int n_in,
                              void* d_out, int out_size) {
    const float* in = (const float*)d_in[0];
    float* out = (float*)d_out;

    const int C = out_size / 2;       // 1024
    const int N = in_sizes[0] / C;    // 32768

    if ((N & 3) == 0 && ((N >> 2) & 511) == 0) {
        const int N4 = N >> 2;
        if ((C & 1) == 0) {
            minmax_pair_kernel<<<C / 2, 512>>>((const float4*)in, out, C, N4);
        } else {
            minmax_final_kernel<<<C, 512>>>((const float4*)in, out, C, N4);
        }
    } else {
        minmax_simple_kernel<<<C, 256>>>(in, out, C, N);
    }
}